// round 1
// baseline (speedup 1.0000x reference)
#include <cuda_runtime.h>
#include <cstdint>

// Batched negative-Pearson loss.
// preds, labels: [B, N] fp32, B=4096, N=8192 (from reference setup_inputs).
// out: scalar fp32 = mean_b(1 - pearson_b).
//
// Pass 1: one CTA per row -> 5 sums -> per-row (1 - pearson) into scratch.
// Pass 2: single CTA deterministic reduction -> mean -> d_out[0].

#define ROW_N 8192
#define MAX_B 4096
#define TPB   256
#define V4_PER_ROW (ROW_N / 4)        // 2048
#define V4_PER_THREAD (V4_PER_ROW / TPB) // 8

__device__ float g_row_loss[MAX_B];

__device__ __forceinline__ float warp_sum(float v) {
    #pragma unroll
    for (int off = 16; off > 0; off >>= 1)
        v += __shfl_down_sync(0xffffffffu, v, off);
    return v;
}

__global__ __launch_bounds__(TPB, 8)
void np_row_kernel(const float* __restrict__ preds,
                   const float* __restrict__ labels) {
    const int row = blockIdx.x;
    const float4* __restrict__ p =
        reinterpret_cast<const float4*>(preds + (size_t)row * ROW_N);
    const float4* __restrict__ l =
        reinterpret_cast<const float4*>(labels + (size_t)row * ROW_N);

    float sx = 0.f, sy = 0.f, sxy = 0.f, sxx = 0.f, syy = 0.f;

    // 8 independent float4 loads per input -> 16 LDG.128 in flight per thread.
    float4 a[V4_PER_THREAD];
    float4 b[V4_PER_THREAD];
    #pragma unroll
    for (int k = 0; k < V4_PER_THREAD; k++)
        a[k] = p[threadIdx.x + k * TPB];
    #pragma unroll
    for (int k = 0; k < V4_PER_THREAD; k++)
        b[k] = l[threadIdx.x + k * TPB];

    #pragma unroll
    for (int k = 0; k < V4_PER_THREAD; k++) {
        sx  += a[k].x + a[k].y + a[k].z + a[k].w;
        sy  += b[k].x + b[k].y + b[k].z + b[k].w;
        sxy = fmaf(a[k].x, b[k].x, sxy);
        sxy = fmaf(a[k].y, b[k].y, sxy);
        sxy = fmaf(a[k].z, b[k].z, sxy);
        sxy = fmaf(a[k].w, b[k].w, sxy);
        sxx = fmaf(a[k].x, a[k].x, sxx);
        sxx = fmaf(a[k].y, a[k].y, sxx);
        sxx = fmaf(a[k].z, a[k].z, sxx);
        sxx = fmaf(a[k].w, a[k].w, sxx);
        syy = fmaf(b[k].x, b[k].x, syy);
        syy = fmaf(b[k].y, b[k].y, syy);
        syy = fmaf(b[k].z, b[k].z, syy);
        syy = fmaf(b[k].w, b[k].w, syy);
    }

    // Intra-warp reduction.
    sx  = warp_sum(sx);
    sy  = warp_sum(sy);
    sxy = warp_sum(sxy);
    sxx = warp_sum(sxx);
    syy = warp_sum(syy);

    __shared__ float sh[5][TPB / 32];
    const int lane = threadIdx.x & 31;
    const int wid  = threadIdx.x >> 5;
    if (lane == 0) {
        sh[0][wid] = sx;  sh[1][wid] = sy;  sh[2][wid] = sxy;
        sh[3][wid] = sxx; sh[4][wid] = syy;
    }
    __syncthreads();

    if (wid == 0) {
        const int nw = TPB / 32; // 8
        float vx  = (lane < nw) ? sh[0][lane] : 0.f;
        float vy  = (lane < nw) ? sh[1][lane] : 0.f;
        float vxy = (lane < nw) ? sh[2][lane] : 0.f;
        float vxx = (lane < nw) ? sh[3][lane] : 0.f;
        float vyy = (lane < nw) ? sh[4][lane] : 0.f;
        #pragma unroll
        for (int off = 4; off > 0; off >>= 1) {
            vx  += __shfl_down_sync(0xffffffffu, vx,  off);
            vy  += __shfl_down_sync(0xffffffffu, vy,  off);
            vxy += __shfl_down_sync(0xffffffffu, vxy, off);
            vxx += __shfl_down_sync(0xffffffffu, vxx, off);
            vyy += __shfl_down_sync(0xffffffffu, vyy, off);
        }
        if (lane == 0) {
            const float Nf = (float)ROW_N;
            float num = Nf * vxy - vx * vy;
            float den = sqrtf((Nf * vxx - vx * vx) * (Nf * vyy - vy * vy));
            g_row_loss[row] = 1.0f - num / den;
        }
    }
}

__global__ __launch_bounds__(TPB, 1)
void np_final_kernel(float* __restrict__ out, int B) {
    float s = 0.f;
    for (int i = threadIdx.x; i < B; i += TPB)
        s = s + g_row_loss[i];

    s = warp_sum(s);
    __shared__ float sh[TPB / 32];
    const int lane = threadIdx.x & 31;
    const int wid  = threadIdx.x >> 5;
    if (lane == 0) sh[wid] = s;
    __syncthreads();
    if (threadIdx.x == 0) {
        float t = 0.f;
        #pragma unroll
        for (int w = 0; w < TPB / 32; w++) t += sh[w];
        out[0] = t / (float)B;
    }
}

extern "C" void kernel_launch(void* const* d_in, const int* in_sizes, int n_in,
                              void* d_out, int out_size) {
    const float* preds  = (const float*)d_in[0];
    const float* labels = (const float*)d_in[1];
    float* out = (float*)d_out;

    const int total = in_sizes[0];
    const int B = total / ROW_N; // 4096

    np_row_kernel<<<B, TPB>>>(preds, labels);
    np_final_kernel<<<1, TPB>>>(out, B);
}

// round 3
// speedup vs baseline: 1.0088x; 1.0088x over previous
#include <cuda_runtime.h>
#include <cstdint>

// Batched negative-Pearson loss, single fused kernel.
// preds, labels: [B, N] fp32, B=4096, N=8192.
// out scalar = mean_b(1 - pearson_b).
//
// One CTA per row -> 5 sums -> per-row loss into scratch. Last CTA to
// finish (atomic ticket) reduces all rows in fixed order -> mean -> out.
// Ticket counter is reset by the last CTA so graph replay is clean.

#define ROW_N 8192
#define MAX_B 4096
#define TPB   256
#define V4_PER_THREAD ((ROW_N / 4) / TPB) // 8

__device__ float g_row_loss[MAX_B];
__device__ unsigned int g_ticket; // zero-initialized; always returned to 0

__device__ __forceinline__ float warp_sum(float v) {
    #pragma unroll
    for (int off = 16; off > 0; off >>= 1)
        v += __shfl_down_sync(0xffffffffu, v, off);
    return v;
}

__global__ __launch_bounds__(TPB, 8)
void np_fused_kernel(const float* __restrict__ preds,
                     const float* __restrict__ labels,
                     float* __restrict__ out, int B) {
    const int row = blockIdx.x;
    const float4* __restrict__ p =
        reinterpret_cast<const float4*>(preds + (size_t)row * ROW_N);
    const float4* __restrict__ l =
        reinterpret_cast<const float4*>(labels + (size_t)row * ROW_N);

    float sx = 0.f, sy = 0.f, sxy = 0.f, sxx = 0.f, syy = 0.f;

    float4 a[V4_PER_THREAD];
    float4 b[V4_PER_THREAD];
    #pragma unroll
    for (int k = 0; k < V4_PER_THREAD; k++)
        a[k] = p[threadIdx.x + k * TPB];
    #pragma unroll
    for (int k = 0; k < V4_PER_THREAD; k++)
        b[k] = l[threadIdx.x + k * TPB];

    #pragma unroll
    for (int k = 0; k < V4_PER_THREAD; k++) {
        sx  += a[k].x + a[k].y + a[k].z + a[k].w;
        sy  += b[k].x + b[k].y + b[k].z + b[k].w;
        sxy = fmaf(a[k].x, b[k].x, sxy);
        sxy = fmaf(a[k].y, b[k].y, sxy);
        sxy = fmaf(a[k].z, b[k].z, sxy);
        sxy = fmaf(a[k].w, b[k].w, sxy);
        sxx = fmaf(a[k].x, a[k].x, sxx);
        sxx = fmaf(a[k].y, a[k].y, sxx);
        sxx = fmaf(a[k].z, a[k].z, sxx);
        sxx = fmaf(a[k].w, a[k].w, sxx);
        syy = fmaf(b[k].x, b[k].x, syy);
        syy = fmaf(b[k].y, b[k].y, syy);
        syy = fmaf(b[k].z, b[k].z, syy);
        syy = fmaf(b[k].w, b[k].w, syy);
    }

    sx  = warp_sum(sx);
    sy  = warp_sum(sy);
    sxy = warp_sum(sxy);
    sxx = warp_sum(sxx);
    syy = warp_sum(syy);

    __shared__ float sh[5][TPB / 32];
    __shared__ bool is_last;
    const int lane = threadIdx.x & 31;
    const int wid  = threadIdx.x >> 5;
    if (lane == 0) {
        sh[0][wid] = sx;  sh[1][wid] = sy;  sh[2][wid] = sxy;
        sh[3][wid] = sxx; sh[4][wid] = syy;
    }
    __syncthreads();

    if (wid == 0) {
        const int nw = TPB / 32;
        float vx  = (lane < nw) ? sh[0][lane] : 0.f;
        float vy  = (lane < nw) ? sh[1][lane] : 0.f;
        float vxy = (lane < nw) ? sh[2][lane] : 0.f;
        float vxx = (lane < nw) ? sh[3][lane] : 0.f;
        float vyy = (lane < nw) ? sh[4][lane] : 0.f;
        #pragma unroll
        for (int off = 4; off > 0; off >>= 1) {
            vx  += __shfl_down_sync(0xffffffffu, vx,  off);
            vy  += __shfl_down_sync(0xffffffffu, vy,  off);
            vxy += __shfl_down_sync(0xffffffffu, vxy, off);
            vxx += __shfl_down_sync(0xffffffffu, vxx, off);
            vyy += __shfl_down_sync(0xffffffffu, vyy, off);
        }
        if (lane == 0) {
            const float Nf = (float)ROW_N;
            float num = Nf * vxy - vx * vy;
            float den = sqrtf((Nf * vxx - vx * vx) * (Nf * vyy - vy * vy));
            g_row_loss[row] = 1.0f - num / den;
            __threadfence();
            unsigned int old = atomicAdd(&g_ticket, 1u);
            is_last = (old == (unsigned int)(gridDim.x - 1));
        }
    }
    __syncthreads();

    if (!is_last) return;

    // Last CTA: all row losses are globally visible (fence + atomic
    // release/acquire chain). Fixed-order reduction -> deterministic.
    float s = 0.f;
    for (int i = threadIdx.x; i < B; i += TPB) {
        float v;
        // .cg: bypass (possibly stale) per-SM L1.
        asm volatile("ld.global.cg.f32 %0, [%1];"
                     : "=f"(v) : "l"(&g_row_loss[i]));
        s += v;
    }
    s = warp_sum(s);
    __shared__ float shf[TPB / 32];
    if (lane == 0) shf[wid] = s;
    __syncthreads();
    if (threadIdx.x == 0) {
        float t = 0.f;
        #pragma unroll
        for (int w = 0; w < TPB / 32; w++) t += shf[w];
        out[0] = t / (float)B;
        g_ticket = 0u; // reset for next graph replay
    }
}

extern "C" void kernel_launch(void* const* d_in, const int* in_sizes, int n_in,
                              void* d_out, int out_size) {
    const float* preds  = (const float*)d_in[0];
    const float* labels = (const float*)d_in[1];
    float* out = (float*)d_out;

    const int B = in_sizes[0] / ROW_N; // 4096
    np_fused_kernel<<<B, TPB>>>(preds, labels, out, B);
}

// round 7
// speedup vs baseline: 1.0384x; 1.0293x over previous
#include <cuda_runtime.h>
#include <cstdint>

// Batched negative-Pearson loss, single fused kernel, streaming L2 policy.
// preds, labels: [B, N] fp32, B=4096, N=8192. out = mean_b(1 - pearson_b).

#define ROW_N 8192
#define MAX_B 4096
#define TPB   256
#define V4_PER_THREAD ((ROW_N / 4) / TPB) // 8

__device__ float g_row_loss[MAX_B];
__device__ unsigned int g_ticket; // zero-init; restored to 0 every launch

__device__ __forceinline__ float warp_sum(float v) {
    #pragma unroll
    for (int off = 16; off > 0; off >>= 1)
        v += __shfl_down_sync(0xffffffffu, v, off);
    return v;
}

__device__ __forceinline__ float4 ldcs4(const float4* p) {
    float4 r;
    asm volatile("ld.global.cs.v4.f32 {%0,%1,%2,%3}, [%4];"
                 : "=f"(r.x), "=f"(r.y), "=f"(r.z), "=f"(r.w)
                 : "l"(p));
    return r;
}

__global__ __launch_bounds__(TPB, 8)
void np_fused_kernel(const float* __restrict__ preds,
                     const float* __restrict__ labels,
                     float* __restrict__ out, int B) {
    const int row = blockIdx.x;
    const float4* __restrict__ p =
        reinterpret_cast<const float4*>(preds + (size_t)row * ROW_N);
    const float4* __restrict__ l =
        reinterpret_cast<const float4*>(labels + (size_t)row * ROW_N);

    float sx = 0.f, sy = 0.f, sxy = 0.f, sxx = 0.f, syy = 0.f;

    // Interleaved unrolled stream: ptxas schedules loads ahead of use,
    // ~16 LDG.128 in flight per thread at 32-reg budget. .cs = evict-first
    // in L2 (pure streaming data, zero reuse).
    #pragma unroll
    for (int k = 0; k < V4_PER_THREAD; k++) {
        float4 a = ldcs4(p + threadIdx.x + k * TPB);
        float4 b = ldcs4(l + threadIdx.x + k * TPB);
        sx  += a.x + a.y + a.z + a.w;
        sy  += b.x + b.y + b.z + b.w;
        sxy = fmaf(a.x, b.x, sxy);
        sxy = fmaf(a.y, b.y, sxy);
        sxy = fmaf(a.z, b.z, sxy);
        sxy = fmaf(a.w, b.w, sxy);
        sxx = fmaf(a.x, a.x, sxx);
        sxx = fmaf(a.y, a.y, sxx);
        sxx = fmaf(a.z, a.z, sxx);
        sxx = fmaf(a.w, a.w, sxx);
        syy = fmaf(b.x, b.x, syy);
        syy = fmaf(b.y, b.y, syy);
        syy = fmaf(b.z, b.z, syy);
        syy = fmaf(b.w, b.w, syy);
    }

    sx  = warp_sum(sx);
    sy  = warp_sum(sy);
    sxy = warp_sum(sxy);
    sxx = warp_sum(sxx);
    syy = warp_sum(syy);

    __shared__ float sh[5][TPB / 32];
    __shared__ bool is_last;
    const int lane = threadIdx.x & 31;
    const int wid  = threadIdx.x >> 5;
    if (lane == 0) {
        sh[0][wid] = sx;  sh[1][wid] = sy;  sh[2][wid] = sxy;
        sh[3][wid] = sxx; sh[4][wid] = syy;
    }
    __syncthreads();

    if (wid == 0) {
        const int nw = TPB / 32;
        float vx  = (lane < nw) ? sh[0][lane] : 0.f;
        float vy  = (lane < nw) ? sh[1][lane] : 0.f;
        float vxy = (lane < nw) ? sh[2][lane] : 0.f;
        float vxx = (lane < nw) ? sh[3][lane] : 0.f;
        float vyy = (lane < nw) ? sh[4][lane] : 0.f;
        #pragma unroll
        for (int off = 4; off > 0; off >>= 1) {
            vx  += __shfl_down_sync(0xffffffffu, vx,  off);
            vy  += __shfl_down_sync(0xffffffffu, vy,  off);
            vxy += __shfl_down_sync(0xffffffffu, vxy, off);
            vxx += __shfl_down_sync(0xffffffffu, vxx, off);
            vyy += __shfl_down_sync(0xffffffffu, vyy, off);
        }
        if (lane == 0) {
            const float Nf = (float)ROW_N;
            float num = Nf * vxy - vx * vy;
            float den = sqrtf((Nf * vxx - vx * vx) * (Nf * vyy - vy * vy));
            g_row_loss[row] = 1.0f - num / den;
            __threadfence();
            unsigned int old = atomicAdd(&g_ticket, 1u);
            is_last = (old == (unsigned int)(gridDim.x - 1));
        }
    }
    __syncthreads();

    if (!is_last) return;

    // Last CTA: all row losses globally visible (fence + atomic chain).
    // Vectorized fixed-order reduction (B/4 float4 = 1024, 4 per thread).
    float s = 0.f;
    const float4* rl = reinterpret_cast<const float4*>(g_row_loss);
    for (int i = threadIdx.x; i < B / 4; i += TPB) {
        float4 v;
        asm volatile("ld.global.cg.v4.f32 {%0,%1,%2,%3}, [%4];"
                     : "=f"(v.x), "=f"(v.y), "=f"(v.z), "=f"(v.w)
                     : "l"(rl + i));
        s += (v.x + v.y) + (v.z + v.w);
    }
    s = warp_sum(s);
    __shared__ float shf[TPB / 32];
    if (lane == 0) shf[wid] = s;
    __syncthreads();
    if (threadIdx.x == 0) {
        float t = 0.f;
        #pragma unroll
        for (int w = 0; w < TPB / 32; w++) t += shf[w];
        out[0] = t / (float)B;
        g_ticket = 0u; // reset for next graph replay
    }
}

extern "C" void kernel_launch(void* const* d_in, const int* in_sizes, int n_in,
                              void* d_out, int out_size) {
    const float* preds  = (const float*)d_in[0];
    const float* labels = (const float*)d_in[1];
    float* out = (float*)d_out;

    const int B = in_sizes[0] / ROW_N; // 4096
    np_fused_kernel<<<B, TPB>>>(preds, labels, out, B);
}